// round 1
// baseline (speedup 1.0000x reference)
#include <cuda_runtime.h>
#include <cstdint>

#define BB 2
#define NSEQ 2048
#define DD 256
#define HH 8
#define DH 32
#define SCALE 0.17677669529663687f  // 1/sqrt(32)

// ---------------- device scratch (no allocations allowed) ----------------
__device__ float g_X[BB * NSEQ * DD];                      // current features
__device__ float g_Q[BB * NSEQ * DD];
__device__ float g_K[BB * NSEQ * DD];
__device__ float g_V[BB * NSEQ * DD];
__device__ float g_O[BB * NSEQ * DD];
__device__ float g_T[BB * NSEQ * DD];
__device__ float g_E[(size_t)BB * HH * NSEQ * NSEQ];       // exp(masked scores), unnormalized (268MB)
__device__ float g_RSI[BB * HH * NSEQ];                    // reciprocal row sums
__device__ float g_A0[(size_t)BB * NSEQ * NSEQ];           // head-avg attention layer0
__device__ float g_A1[(size_t)BB * NSEQ * NSEQ];           // head-avg attention layer1
__device__ unsigned g_MB[NSEQ * (NSEQ / 32)];              // adjacency bitmask

// ---------------- adjacency -> bitmask ----------------
__global__ void k_maskbits(const float* __restrict__ adj, unsigned* __restrict__ mb) {
    int w = blockIdx.x * blockDim.x + threadIdx.x;
    if (w >= NSEQ * (NSEQ / 32)) return;
    int i = w >> 6;
    int c = w & 63;
    const float* row = adj + (size_t)i * NSEQ + c * 32;
    unsigned bits = 0;
#pragma unroll
    for (int t = 0; t < 32; t++) bits |= (row[t] > 0.0f) ? (1u << t) : 0u;
    mb[w] = bits;
}

// ---------------- projection GEMM: C[m,n] = sum_k A[m,k] * W[n,k] ----------------
// A: [4096, 256], W: [256, 256] row-major (NT). blockIdx.z selects (W, C) pair.
__global__ __launch_bounds__(256) void k_proj(
    const float* __restrict__ A,
    const float* __restrict__ W0, const float* __restrict__ W1, const float* __restrict__ W2,
    float* __restrict__ C0, float* __restrict__ C1, float* __restrict__ C2)
{
    const float* W = (blockIdx.z == 0) ? W0 : ((blockIdx.z == 1) ? W1 : W2);
    float* C       = (blockIdx.z == 0) ? C0 : ((blockIdx.z == 1) ? C1 : C2);
    int m0 = blockIdx.x * 64;
    int n0 = blockIdx.y * 64;
    __shared__ float As[16][65];
    __shared__ float Bs[16][65];
    int t  = threadIdx.x;
    int lr = t >> 2;            // 0..63
    int lk = (t & 3) * 4;       // 0,4,8,12
    int ty = t >> 4;            // 0..15
    int tx = t & 15;            // 0..15
    float acc[4][4] = {};
    for (int k0 = 0; k0 < 256; k0 += 16) {
        float4 a = *(const float4*)(A + (size_t)(m0 + lr) * 256 + k0 + lk);
        float4 w = *(const float4*)(W + (size_t)(n0 + lr) * 256 + k0 + lk);
        __syncthreads();
        As[lk + 0][lr] = a.x; As[lk + 1][lr] = a.y; As[lk + 2][lr] = a.z; As[lk + 3][lr] = a.w;
        Bs[lk + 0][lr] = w.x; Bs[lk + 1][lr] = w.y; Bs[lk + 2][lr] = w.z; Bs[lk + 3][lr] = w.w;
        __syncthreads();
#pragma unroll
        for (int kk = 0; kk < 16; kk++) {
            float av[4], bv[4];
#pragma unroll
            for (int r = 0; r < 4; r++) av[r] = As[kk][ty + 16 * r];
#pragma unroll
            for (int c = 0; c < 4; c++) bv[c] = Bs[kk][tx + 16 * c];
#pragma unroll
            for (int r = 0; r < 4; r++)
#pragma unroll
                for (int c = 0; c < 4; c++) acc[r][c] += av[r] * bv[c];
        }
    }
#pragma unroll
    for (int r = 0; r < 4; r++)
#pragma unroll
        for (int c = 0; c < 4; c++)
            C[(size_t)(m0 + ty + 16 * r) * 256 + n0 + tx + 16 * c] = acc[r][c];
}

// ---------------- scores + mask + exp + rowsum ----------------
// E[bh,i,j] = mask ? exp(scale * q_i . k_j) : 0 ;  RSI[bh,i] = 1/sum_j E
__global__ __launch_bounds__(256) void k_scores(
    const float* __restrict__ Q, const float* __restrict__ Kmat,
    const unsigned* __restrict__ mb,
    float* __restrict__ E, float* __restrict__ RSI)
{
    int bh = blockIdx.y;           // 0..15
    int b  = bh >> 3;
    int h  = bh & 7;
    int i0 = blockIdx.x * 32;
    __shared__ float qs[32][33];
    __shared__ float ks[128][33];
    int t  = threadIdx.x;
    int ty = t >> 5;               // 0..7 warp id
    int tx = t & 31;               // lane

    // load 32x32 q tile
#pragma unroll
    for (int l = 0; l < 4; l++) {
        int idx = t + 256 * l;
        int i = idx >> 5, d = idx & 31;
        qs[i][d] = Q[((size_t)(b * NSEQ + i0 + i)) * DD + h * 32 + d];
    }

    float acc_sum[4] = {0.f, 0.f, 0.f, 0.f};

    for (int jc = 0; jc < NSEQ / 128; jc++) {
        int j0 = jc * 128;
        __syncthreads();
#pragma unroll
        for (int l = 0; l < 16; l++) {
            int idx = t + 256 * l;
            int j = idx >> 5, d = idx & 31;
            ks[j][d] = Kmat[((size_t)(b * NSEQ + j0 + j)) * DD + h * 32 + d];
        }
        __syncthreads();

        float sc[4][4] = {};
#pragma unroll
        for (int d = 0; d < 32; d++) {
            float qv[4], kv[4];
#pragma unroll
            for (int r = 0; r < 4; r++) qv[r] = qs[ty * 4 + r][d];
#pragma unroll
            for (int c = 0; c < 4; c++) kv[c] = ks[tx + 32 * c][d];
#pragma unroll
            for (int r = 0; r < 4; r++)
#pragma unroll
                for (int c = 0; c < 4; c++) sc[r][c] += qv[r] * kv[c];
        }
#pragma unroll
        for (int r = 0; r < 4; r++) {
            int gi = i0 + ty * 4 + r;
#pragma unroll
            for (int c = 0; c < 4; c++) {
                int gj = j0 + tx + 32 * c;
                unsigned bits = mb[gi * 64 + (gj >> 5)];
                float e = ((bits >> tx) & 1u) ? __expf(sc[r][c] * SCALE) : 0.0f;
                acc_sum[r] += e;
                E[((size_t)bh * NSEQ + gi) * NSEQ + gj] = e;
            }
        }
    }
    // warp-reduce row sums (each warp owns rows ty*4 .. ty*4+3 over all lanes)
#pragma unroll
    for (int r = 0; r < 4; r++) {
        float s = acc_sum[r];
#pragma unroll
        for (int off = 16; off > 0; off >>= 1) s += __shfl_xor_sync(0xffffffffu, s, off);
        if (tx == 0) RSI[bh * NSEQ + i0 + ty * 4 + r] = 1.0f / s;
    }
}

// ---------------- PV: O[b,i,h*32+d] = RSI[bh,i] * sum_j E[bh,i,j] * V[b,j,h*32+d] ----------------
__global__ __launch_bounds__(128) void k_pv(
    const float* __restrict__ E, const float* __restrict__ RSI,
    const float* __restrict__ V, float* __restrict__ O)
{
    int bh = blockIdx.y;
    int b  = bh >> 3;
    int h  = bh & 7;
    int i0 = blockIdx.x * 64;
    __shared__ float Es[64][65];
    __shared__ __align__(16) float Vs[64][33];
    int t  = threadIdx.x;
    int ty = t >> 3;              // 0..15
    int tx = t & 7;               // 0..7
    float acc[4][4] = {};

    for (int jc = 0; jc < NSEQ / 64; jc++) {
        int j0 = jc * 64;
        __syncthreads();
#pragma unroll
        for (int l = 0; l < 8; l++) {
            int idx = t + 128 * l;
            int row = idx >> 4, j4 = (idx & 15) * 4;
            float4 e = *(const float4*)(E + ((size_t)bh * NSEQ + i0 + row) * NSEQ + j0 + j4);
            Es[row][j4 + 0] = e.x; Es[row][j4 + 1] = e.y; Es[row][j4 + 2] = e.z; Es[row][j4 + 3] = e.w;
        }
#pragma unroll
        for (int l = 0; l < 4; l++) {
            int idx = t + 128 * l;
            int j = idx >> 3, d4 = (idx & 7) * 4;
            float4 v = *(const float4*)(V + ((size_t)(b * NSEQ + j0 + j)) * DD + h * 32 + d4);
            Vs[j][d4 + 0] = v.x; Vs[j][d4 + 1] = v.y; Vs[j][d4 + 2] = v.z; Vs[j][d4 + 3] = v.w;
        }
        __syncthreads();
#pragma unroll 16
        for (int j = 0; j < 64; j++) {
            float ev[4], vv[4];
#pragma unroll
            for (int r = 0; r < 4; r++) ev[r] = Es[ty + 16 * r][j];
#pragma unroll
            for (int c = 0; c < 4; c++) vv[c] = Vs[j][tx + 8 * c];
#pragma unroll
            for (int r = 0; r < 4; r++)
#pragma unroll
                for (int c = 0; c < 4; c++) acc[r][c] += ev[r] * vv[c];
        }
    }
#pragma unroll
    for (int r = 0; r < 4; r++) {
        int gi = i0 + ty + 16 * r;
        float inv = RSI[bh * NSEQ + gi];
#pragma unroll
        for (int c = 0; c < 4; c++)
            O[((size_t)(b * NSEQ + gi)) * DD + h * 32 + tx + 8 * c] = acc[r][c] * inv;
    }
}

// ---------------- head-averaged attention: A[b,i,j] = (1/8) * sum_h E/rowsum ----------------
__global__ void k_aagg(const float* __restrict__ E, const float* __restrict__ RSI,
                       float* __restrict__ A)
{
    int idx = blockIdx.x * blockDim.x + threadIdx.x;   // over BB*NSEQ*(NSEQ/4)
    int total = BB * NSEQ * (NSEQ / 4);
    if (idx >= total) return;
    int j4 = idx & (NSEQ / 4 - 1);
    int i  = (idx >> 9) & (NSEQ - 1);
    int b  = idx >> 20;
    float4 acc = make_float4(0.f, 0.f, 0.f, 0.f);
#pragma unroll
    for (int h = 0; h < HH; h++) {
        int bh = b * HH + h;
        float w = RSI[bh * NSEQ + i];
        float4 e = *(const float4*)(E + ((size_t)bh * NSEQ + i) * NSEQ + j4 * 4);
        acc.x += e.x * w; acc.y += e.y * w; acc.z += e.z * w; acc.w += e.w * w;
    }
    acc.x *= 0.125f; acc.y *= 0.125f; acc.z *= 0.125f; acc.w *= 0.125f;
    *(float4*)(A + ((size_t)b * NSEQ + i) * NSEQ + j4 * 4) = acc;
}

// ---------------- residual + layernorm (in place on X) ----------------
__global__ void k_addln(float* __restrict__ X, const float* __restrict__ T,
                        const float* __restrict__ g, const float* __restrict__ bta)
{
    int row = blockIdx.x;
    int t = threadIdx.x;
    float v = X[row * 256 + t] + T[row * 256 + t];
    float s = v, s2 = v * v;
#pragma unroll
    for (int off = 16; off > 0; off >>= 1) {
        s  += __shfl_xor_sync(0xffffffffu, s, off);
        s2 += __shfl_xor_sync(0xffffffffu, s2, off);
    }
    __shared__ float red[16];
    __shared__ float mu_s, rstd_s;
    int w = t >> 5, lane = t & 31;
    if (lane == 0) { red[w] = s; red[8 + w] = s2; }
    __syncthreads();
    if (t == 0) {
        float S = 0.f, S2 = 0.f;
#pragma unroll
        for (int i = 0; i < 8; i++) { S += red[i]; S2 += red[8 + i]; }
        float mu = S * (1.0f / 256.0f);
        float var = S2 * (1.0f / 256.0f) - mu * mu;
        mu_s = mu;
        rstd_s = rsqrtf(var + 1e-5f);
    }
    __syncthreads();
    X[row * 256 + t] = (v - mu_s) * rstd_s * g[t] + bta[t];
}

// ---------------- chain GEMM (NN, per batch): C = A @ B, 2048^3 ----------------
__global__ __launch_bounds__(256) void k_chain(
    const float* __restrict__ A, const float* __restrict__ B, float* __restrict__ C)
{
    int bb = blockIdx.z;
    const float* Ab = A + (size_t)bb * NSEQ * NSEQ;
    const float* Bb = B + (size_t)bb * NSEQ * NSEQ;
    float* Cb = C + (size_t)bb * NSEQ * NSEQ;
    int m0 = blockIdx.y * 128;
    int n0 = blockIdx.x * 128;
    __shared__ __align__(16) float As[16][132];
    __shared__ __align__(16) float Bs[16][132];
    int t = threadIdx.x;
    int ty = t >> 4, tx = t & 15;
    int ar = t >> 2, ak = (t & 3) * 4;        // A tile: rows ar, ar+64 ; k cols ak..ak+3
    int bk = t >> 5, bn = (t & 31) * 4;       // B tile: k rows bk, bk+8 ; n cols bn..bn+3
    float acc[8][8] = {};
    for (int k0 = 0; k0 < NSEQ; k0 += 16) {
        float4 a0 = *(const float4*)(Ab + (size_t)(m0 + ar) * NSEQ + k0 + ak);
        float4 a1 = *(const float4*)(Ab + (size_t)(m0 + ar + 64) * NSEQ + k0 + ak);
        float4 b0 = *(const float4*)(Bb + (size_t)(k0 + bk) * NSEQ + n0 + bn);
        float4 b1 = *(const float4*)(Bb + (size_t)(k0 + bk + 8) * NSEQ + n0 + bn);
        __syncthreads();
        As[ak + 0][ar] = a0.x; As[ak + 1][ar] = a0.y; As[ak + 2][ar] = a0.z; As[ak + 3][ar] = a0.w;
        As[ak + 0][ar + 64] = a1.x; As[ak + 1][ar + 64] = a1.y; As[ak + 2][ar + 64] = a1.z; As[ak + 3][ar + 64] = a1.w;
        *(float4*)&Bs[bk][bn]     = b0;
        *(float4*)&Bs[bk + 8][bn] = b1;
        __syncthreads();
#pragma unroll
        for (int kk = 0; kk < 16; kk++) {
            float av[8], bv[8];
#pragma unroll
            for (int r = 0; r < 8; r++) av[r] = As[kk][ty + 16 * r];
#pragma unroll
            for (int c = 0; c < 8; c++) bv[c] = Bs[kk][tx + 16 * c];
#pragma unroll
            for (int r = 0; r < 8; r++)
#pragma unroll
                for (int c = 0; c < 8; c++) acc[r][c] += av[r] * bv[c];
        }
    }
#pragma unroll
    for (int r = 0; r < 8; r++)
#pragma unroll
        for (int c = 0; c < 8; c++)
            Cb[(size_t)(m0 + ty + 16 * r) * NSEQ + n0 + tx + 16 * c] = acc[r][c];
}

// ---------------- host ----------------
extern "C" void kernel_launch(void* const* d_in, const int* in_sizes, int n_in,
                              void* d_out, int out_size)
{
    const float* x     = (const float*)d_in[0];
    const float* adj   = (const float*)d_in[1];
    const float* Wf0   = (const float*)d_in[2];
    const float* Wq    = (const float*)d_in[3];
    const float* Wk    = (const float*)d_in[4];
    const float* Wv    = (const float*)d_in[5];
    const float* Wo    = (const float*)d_in[6];
    const float* gamma = (const float*)d_in[7];
    const float* beta  = (const float*)d_in[8];
    float* out_x    = (float*)d_out;
    float* out_attn = (float*)d_out + (size_t)BB * NSEQ * DD;

    float *X, *Q, *K, *V, *O, *T, *E, *RSI, *A0, *A1;
    unsigned* MB;
    cudaGetSymbolAddress((void**)&X, g_X);
    cudaGetSymbolAddress((void**)&Q, g_Q);
    cudaGetSymbolAddress((void**)&K, g_K);
    cudaGetSymbolAddress((void**)&V, g_V);
    cudaGetSymbolAddress((void**)&O, g_O);
    cudaGetSymbolAddress((void**)&T, g_T);
    cudaGetSymbolAddress((void**)&E, g_E);
    cudaGetSymbolAddress((void**)&RSI, g_RSI);
    cudaGetSymbolAddress((void**)&A0, g_A0);
    cudaGetSymbolAddress((void**)&A1, g_A1);
    cudaGetSymbolAddress((void**)&MB, g_MB);

    const int WSZ = 256 * 256;  // weight matrix elements per layer

    k_maskbits<<<512, 256>>>(adj, MB);

    // x = x @ Wf0^T
    k_proj<<<dim3(64, 4, 1), 256>>>(x, Wf0, Wf0, Wf0, X, X, X);

    for (int i = 0; i < 2; i++) {
        // Q,K,V projections in one launch (z = 0,1,2)
        k_proj<<<dim3(64, 4, 3), 256>>>(X, Wq + i * WSZ, Wk + i * WSZ, Wv + i * WSZ, Q, K, V);
        // scores -> exp -> rowsums
        k_scores<<<dim3(NSEQ / 32, BB * HH), 256>>>(Q, K, MB, E, RSI);
        // O = softmax(scores) @ V
        k_pv<<<dim3(NSEQ / 64, BB * HH), 128>>>(E, RSI, V, O);
        // T = O @ Wo^T
        k_proj<<<dim3(64, 4, 1), 256>>>(O, Wo + i * WSZ, Wo + i * WSZ, Wo + i * WSZ, T, T, T);
        // X = LN(X + T)
        k_addln<<<BB * NSEQ, 256>>>(X, T, gamma + i * 256, beta + i * 256);
        // head-averaged attention
        k_aagg<<<(BB * NSEQ * (NSEQ / 4) + 255) / 256, 256>>>(E, RSI, (i == 0) ? A0 : A1);
    }

    // atten = A1 @ A0 -> output
    k_chain<<<dim3(NSEQ / 128, NSEQ / 128, BB), 256>>>(A1, A0, out_attn);

    // x -> output
    cudaMemcpyAsync(out_x, X, (size_t)BB * NSEQ * DD * sizeof(float),
                    cudaMemcpyDeviceToDevice);
}

// round 2
// speedup vs baseline: 1.5818x; 1.5818x over previous
#include <cuda_runtime.h>
#include <cstdint>

#define BB 2
#define NSEQ 2048
#define DD 256
#define HH 8
#define DH 32
#define SCALE 0.17677669529663687f  // 1/sqrt(32)

// ---------------- device scratch ----------------
__device__ float g_X[BB * NSEQ * DD];
__device__ float g_Q[BB * NSEQ * DD];
__device__ float g_K[BB * NSEQ * DD];
__device__ float g_V[BB * NSEQ * DD];
__device__ float g_O[BB * NSEQ * DD];
__device__ float g_T[BB * NSEQ * DD];
__device__ float g_E[(size_t)BB * HH * NSEQ * NSEQ];   // exp(masked scores), unnormalized
__device__ float g_RSI[BB * HH * NSEQ];                // reciprocal row sums
__device__ float g_A0[(size_t)BB * NSEQ * NSEQ];       // head-avg attention layer0 (tf32-rounded)
__device__ float g_A1[(size_t)BB * NSEQ * NSEQ];       // head-avg attention layer1 (tf32-rounded)
__device__ unsigned g_MB[NSEQ * (NSEQ / 32)];          // adjacency bitmask

// tf32 round-to-nearest helper (value keeps fp32 type, low mantissa bits zeroed)
__device__ __forceinline__ float f2tf32(float x) {
    unsigned u;
    asm("cvt.rna.tf32.f32 %0, %1;" : "=r"(u) : "f"(x));
    return __uint_as_float(u);
}

__device__ __forceinline__ void mma_tf32(float d[4], const unsigned a[4], const unsigned b[2]) {
    asm volatile(
        "mma.sync.aligned.m16n8k8.row.col.f32.tf32.tf32.f32 "
        "{%0,%1,%2,%3}, {%4,%5,%6,%7}, {%8,%9}, {%0,%1,%2,%3};"
        : "+f"(d[0]), "+f"(d[1]), "+f"(d[2]), "+f"(d[3])
        : "r"(a[0]), "r"(a[1]), "r"(a[2]), "r"(a[3]), "r"(b[0]), "r"(b[1]));
}

// ---------------- adjacency -> bitmask ----------------
__global__ void k_maskbits(const float* __restrict__ adj, unsigned* __restrict__ mb) {
    int w = blockIdx.x * blockDim.x + threadIdx.x;
    if (w >= NSEQ * (NSEQ / 32)) return;
    int i = w >> 6;
    int c = w & 63;
    const float* row = adj + (size_t)i * NSEQ + c * 32;
    unsigned bits = 0;
#pragma unroll
    for (int t = 0; t < 32; t++) bits |= (row[t] > 0.0f) ? (1u << t) : 0u;
    mb[w] = bits;
}

// ---------------- projection GEMM: C[m,n] = sum_k A[m,k] * W[n,k] (NT) ----------------
__global__ __launch_bounds__(256) void k_proj(
    const float* __restrict__ A,
    const float* __restrict__ W0, const float* __restrict__ W1, const float* __restrict__ W2,
    float* __restrict__ C0, float* __restrict__ C1, float* __restrict__ C2)
{
    const float* W = (blockIdx.z == 0) ? W0 : ((blockIdx.z == 1) ? W1 : W2);
    float* C       = (blockIdx.z == 0) ? C0 : ((blockIdx.z == 1) ? C1 : C2);
    int m0 = blockIdx.x * 64;
    int n0 = blockIdx.y * 64;
    __shared__ float As[16][65];
    __shared__ float Bs[16][65];
    int t  = threadIdx.x;
    int lr = t >> 2;
    int lk = (t & 3) * 4;
    int ty = t >> 4;
    int tx = t & 15;
    float acc[4][4] = {};
    for (int k0 = 0; k0 < 256; k0 += 16) {
        float4 a = *(const float4*)(A + (size_t)(m0 + lr) * 256 + k0 + lk);
        float4 w = *(const float4*)(W + (size_t)(n0 + lr) * 256 + k0 + lk);
        __syncthreads();
        As[lk + 0][lr] = a.x; As[lk + 1][lr] = a.y; As[lk + 2][lr] = a.z; As[lk + 3][lr] = a.w;
        Bs[lk + 0][lr] = w.x; Bs[lk + 1][lr] = w.y; Bs[lk + 2][lr] = w.z; Bs[lk + 3][lr] = w.w;
        __syncthreads();
#pragma unroll
        for (int kk = 0; kk < 16; kk++) {
            float av[4], bv[4];
#pragma unroll
            for (int r = 0; r < 4; r++) av[r] = As[kk][ty + 16 * r];
#pragma unroll
            for (int c = 0; c < 4; c++) bv[c] = Bs[kk][tx + 16 * c];
#pragma unroll
            for (int r = 0; r < 4; r++)
#pragma unroll
                for (int c = 0; c < 4; c++) acc[r][c] += av[r] * bv[c];
        }
    }
#pragma unroll
    for (int r = 0; r < 4; r++)
#pragma unroll
        for (int c = 0; c < 4; c++)
            C[(size_t)(m0 + ty + 16 * r) * 256 + n0 + tx + 16 * c] = acc[r][c];
}

// ---------------- scores + mask + exp + rowsum ----------------
__global__ __launch_bounds__(256) void k_scores(
    const float* __restrict__ Q, const float* __restrict__ Kmat,
    const unsigned* __restrict__ mb,
    float* __restrict__ E, float* __restrict__ RSI)
{
    int bh = blockIdx.y;
    int b  = bh >> 3;
    int h  = bh & 7;
    int i0 = blockIdx.x * 32;
    __shared__ float qs[32][33];
    __shared__ float ks[128][33];
    int t  = threadIdx.x;
    int ty = t >> 5;
    int tx = t & 31;

#pragma unroll
    for (int l = 0; l < 4; l++) {
        int idx = t + 256 * l;
        int i = idx >> 5, d = idx & 31;
        qs[i][d] = Q[((size_t)(b * NSEQ + i0 + i)) * DD + h * 32 + d];
    }

    float acc_sum[4] = {0.f, 0.f, 0.f, 0.f};

    for (int jc = 0; jc < NSEQ / 128; jc++) {
        int j0 = jc * 128;
        __syncthreads();
#pragma unroll
        for (int l = 0; l < 16; l++) {
            int idx = t + 256 * l;
            int j = idx >> 5, d = idx & 31;
            ks[j][d] = Kmat[((size_t)(b * NSEQ + j0 + j)) * DD + h * 32 + d];
        }
        __syncthreads();

        float sc[4][4] = {};
#pragma unroll
        for (int d = 0; d < 32; d++) {
            float qv[4], kv[4];
#pragma unroll
            for (int r = 0; r < 4; r++) qv[r] = qs[ty * 4 + r][d];
#pragma unroll
            for (int c = 0; c < 4; c++) kv[c] = ks[tx + 32 * c][d];
#pragma unroll
            for (int r = 0; r < 4; r++)
#pragma unroll
                for (int c = 0; c < 4; c++) sc[r][c] += qv[r] * kv[c];
        }
#pragma unroll
        for (int r = 0; r < 4; r++) {
            int gi = i0 + ty * 4 + r;
#pragma unroll
            for (int c = 0; c < 4; c++) {
                int gj = j0 + tx + 32 * c;
                unsigned bits = mb[gi * 64 + (gj >> 5)];
                float e = ((bits >> tx) & 1u) ? __expf(sc[r][c] * SCALE) : 0.0f;
                acc_sum[r] += e;
                E[((size_t)bh * NSEQ + gi) * NSEQ + gj] = e;
            }
        }
    }
#pragma unroll
    for (int r = 0; r < 4; r++) {
        float s = acc_sum[r];
#pragma unroll
        for (int off = 16; off > 0; off >>= 1) s += __shfl_xor_sync(0xffffffffu, s, off);
        if (tx == 0) RSI[bh * NSEQ + i0 + ty * 4 + r] = 1.0f / s;
    }
}

// ---------------- fused PV (tf32 mma) + head-averaged attention ----------------
// block: 512 threads = 16 warps; warp w serves head w/2, row-half w&1.
// block tile: (b, 32 query rows). Reads E once; produces O rows and A tile.
// smem: Es[8][32][68] (tf32), Vs[64][264] (tf32), ws[8][32]
#define ES_STRIDE 68
#define VS_STRIDE 264
#define ES_FLOATS (8 * 32 * ES_STRIDE)
#define VS_FLOATS (64 * VS_STRIDE)
#define PVAGG_SMEM ((ES_FLOATS + VS_FLOATS + 256) * 4)

__global__ __launch_bounds__(512) void k_pvagg(
    const float* __restrict__ E, const float* __restrict__ RSI,
    const float* __restrict__ V, float* __restrict__ O, float* __restrict__ A)
{
    extern __shared__ float sm[];
    float* Es = sm;
    float* Vs = sm + ES_FLOATS;
    float* ws = Vs + VS_FLOATS;

    int b  = blockIdx.y;
    int i0 = blockIdx.x * 32;
    int t  = threadIdx.x;
    int lane = t & 31, warp = t >> 5;
    int h = warp >> 1, s = warp & 1;
    int gid = lane >> 2, tig = lane & 3;
    int ai  = t >> 4;           // 0..31 (aagg row)
    int aj4 = (t & 15) * 4;     // aagg col group

    if (t < 256) {
        int hh = t >> 5, ii = t & 31;
        ws[hh * 32 + ii] = RSI[(b * HH + hh) * NSEQ + i0 + ii];
    }

    float acc[4][4] = {};       // [n-tile][4 regs]

    for (int jt = 0; jt < NSEQ / 64; jt++) {
        int j0 = jt * 64;
        __syncthreads();
        // load E tiles for all 8 heads: 8*32*64 floats = 4096 float4
#pragma unroll
        for (int l = 0; l < 8; l++) {
            int idx = t + 512 * l;
            int eh = idx >> 9, rr = idx & 511;
            int ei = rr >> 4, ej4 = (rr & 15) * 4;
            float4 e = *(const float4*)(E + ((size_t)(b * HH + eh) * NSEQ + i0 + ei) * NSEQ + j0 + ej4);
            e.x = f2tf32(e.x); e.y = f2tf32(e.y); e.z = f2tf32(e.z); e.w = f2tf32(e.w);
            *(float4*)&Es[(eh * 32 + ei) * ES_STRIDE + ej4] = e;
        }
        // load V tile: 64 rows x 256 cols = 4096 float4
#pragma unroll
        for (int l = 0; l < 8; l++) {
            int idx = t + 512 * l;
            int vj = idx >> 6, vd4 = (idx & 63) * 4;
            float4 v = *(const float4*)(V + ((size_t)(b * NSEQ + j0 + vj)) * DD + vd4);
            v.x = f2tf32(v.x); v.y = f2tf32(v.y); v.z = f2tf32(v.z); v.w = f2tf32(v.w);
            *(float4*)&Vs[vj * VS_STRIDE + vd4] = v;
        }
        __syncthreads();

        // head-averaged attention tile: A[i0+ai][j0+aj4..+3]
        {
            float4 aa = make_float4(0.f, 0.f, 0.f, 0.f);
#pragma unroll
            for (int hh = 0; hh < 8; hh++) {
                float w = ws[hh * 32 + ai];
                float4 e = *(const float4*)&Es[(hh * 32 + ai) * ES_STRIDE + aj4];
                aa.x += w * e.x; aa.y += w * e.y; aa.z += w * e.z; aa.w += w * e.w;
            }
            aa.x = f2tf32(aa.x * 0.125f); aa.y = f2tf32(aa.y * 0.125f);
            aa.z = f2tf32(aa.z * 0.125f); aa.w = f2tf32(aa.w * 0.125f);
            *(float4*)(A + ((size_t)b * NSEQ + i0 + ai) * NSEQ + j0 + aj4) = aa;
        }

        // PV mma: warp (h,s): rows s*16 + {gid, gid+8}, cols h*32 + in*8 ...
        int er = h * 32 + s * 16 + gid;    // Es row index (head-local query row)
#pragma unroll
        for (int ks = 0; ks < 64; ks += 8) {
            unsigned af[4];
            af[0] = __float_as_uint(Es[er * ES_STRIDE + ks + tig]);
            af[1] = __float_as_uint(Es[(er + 8) * ES_STRIDE + ks + tig]);
            af[2] = __float_as_uint(Es[er * ES_STRIDE + ks + tig + 4]);
            af[3] = __float_as_uint(Es[(er + 8) * ES_STRIDE + ks + tig + 4]);
#pragma unroll
            for (int in = 0; in < 4; in++) {
                int c = h * 32 + in * 8 + gid;
                unsigned bf[2];
                bf[0] = __float_as_uint(Vs[(ks + tig) * VS_STRIDE + c]);
                bf[1] = __float_as_uint(Vs[(ks + tig + 4) * VS_STRIDE + c]);
                mma_tf32(acc[in], af, bf);
            }
        }
    }

    // epilogue: O[b, i0 + s*16 + gid (+8), h*32 + in*8 + 2*tig (+1)] scaled by RSI
    int r0 = s * 16 + gid;
    float w0 = ws[h * 32 + r0];
    float w1 = ws[h * 32 + r0 + 8];
#pragma unroll
    for (int in = 0; in < 4; in++) {
        int c0 = h * 32 + in * 8 + 2 * tig;
        size_t base = ((size_t)(b * NSEQ + i0 + r0)) * DD + c0;
        float2 o0 = make_float2(acc[in][0] * w0, acc[in][1] * w0);
        *(float2*)(O + base) = o0;
        float2 o1 = make_float2(acc[in][2] * w1, acc[in][3] * w1);
        *(float2*)(O + base + 8 * DD) = o1;
    }
}

// ---------------- residual + layernorm (in place on X) ----------------
__global__ void k_addln(float* __restrict__ X, const float* __restrict__ T,
                        const float* __restrict__ g, const float* __restrict__ bta)
{
    int row = blockIdx.x;
    int t = threadIdx.x;
    float v = X[row * 256 + t] + T[row * 256 + t];
    float s = v, s2 = v * v;
#pragma unroll
    for (int off = 16; off > 0; off >>= 1) {
        s  += __shfl_xor_sync(0xffffffffu, s, off);
        s2 += __shfl_xor_sync(0xffffffffu, s2, off);
    }
    __shared__ float red[16];
    __shared__ float mu_s, rstd_s;
    int w = t >> 5, lane = t & 31;
    if (lane == 0) { red[w] = s; red[8 + w] = s2; }
    __syncthreads();
    if (t == 0) {
        float S = 0.f, S2 = 0.f;
#pragma unroll
        for (int i = 0; i < 8; i++) { S += red[i]; S2 += red[8 + i]; }
        float mu = S * (1.0f / 256.0f);
        float var = S2 * (1.0f / 256.0f) - mu * mu;
        mu_s = mu;
        rstd_s = rsqrtf(var + 1e-5f);
    }
    __syncthreads();
    X[row * 256 + t] = (v - mu_s) * rstd_s * g[t] + bta[t];
}

// ---------------- chain GEMM via tf32 mma, cp.async double-buffered ----------------
// C[b] = A[b] @ B[b], 2048x2048x2048. Inputs pre-rounded to tf32.
#define CH_AS_STRIDE 36
#define CH_BS_STRIDE 136
#define CH_AS_FLOATS (128 * CH_AS_STRIDE)
#define CH_BS_FLOATS (32 * CH_BS_STRIDE)
#define CHAIN_SMEM ((2 * CH_AS_FLOATS + 2 * CH_BS_FLOATS) * 4)

__global__ __launch_bounds__(256, 2) void k_chain_tf32(
    const float* __restrict__ A, const float* __restrict__ B, float* __restrict__ C)
{
    extern __shared__ float sm[];
    float* AsBase = sm;                       // 2 * 128*36
    float* BsBase = sm + 2 * CH_AS_FLOATS;    // 2 * 32*136

    int bb = blockIdx.z;
    const float* Ab = A + (size_t)bb * NSEQ * NSEQ;
    const float* Bb = B + (size_t)bb * NSEQ * NSEQ;
    float* Cb = C + (size_t)bb * NSEQ * NSEQ;

    int t = threadIdx.x;
    int lane = t & 31, warp = t >> 5;
    int gid = lane >> 2, tig = lane & 3;
    int wm = warp >> 2, wn = warp & 3;
    int m0 = blockIdx.y * 128, n0 = blockIdx.x * 128;

    float acc[4][4][4] = {};   // [im][in][4]

    // cp.async issue for one K-tile
    auto issue = [&](int buf, int k0) {
        float* as = AsBase + buf * CH_AS_FLOATS;
        float* bs = BsBase + buf * CH_BS_FLOATS;
#pragma unroll
        for (int l = 0; l < 4; l++) {
            int idx = t + 256 * l;
            int m = idx >> 3, k4 = (idx & 7) * 4;
            const float* src = Ab + (size_t)(m0 + m) * NSEQ + k0 + k4;
            unsigned dst = (unsigned)__cvta_generic_to_shared(&as[m * CH_AS_STRIDE + k4]);
            asm volatile("cp.async.cg.shared.global [%0], [%1], 16;" :: "r"(dst), "l"(src));
        }
#pragma unroll
        for (int l = 0; l < 4; l++) {
            int idx = t + 256 * l;
            int k = idx >> 5, n4 = (idx & 31) * 4;
            const float* src = Bb + (size_t)(k0 + k) * NSEQ + n0 + n4;
            unsigned dst = (unsigned)__cvta_generic_to_shared(&bs[k * CH_BS_STRIDE + n4]);
            asm volatile("cp.async.cg.shared.global [%0], [%1], 16;" :: "r"(dst), "l"(src));
        }
        asm volatile("cp.async.commit_group;");
    };

    issue(0, 0);
    const int NT = NSEQ / 32;
    for (int kt = 0; kt < NT; kt++) {
        int buf = kt & 1;
        if (kt + 1 < NT) {
            issue(buf ^ 1, (kt + 1) * 32);
            asm volatile("cp.async.wait_group 1;");
        } else {
            asm volatile("cp.async.wait_group 0;");
        }
        __syncthreads();

        float* as = AsBase + buf * CH_AS_FLOATS;
        float* bs = BsBase + buf * CH_BS_FLOATS;
#pragma unroll
        for (int ks = 0; ks < 32; ks += 8) {
            unsigned af[4][4], bf[4][2];
#pragma unroll
            for (int im = 0; im < 4; im++) {
                int r = wm * 64 + im * 16 + gid;
                af[im][0] = __float_as_uint(as[r * CH_AS_STRIDE + ks + tig]);
                af[im][1] = __float_as_uint(as[(r + 8) * CH_AS_STRIDE + ks + tig]);
                af[im][2] = __float_as_uint(as[r * CH_AS_STRIDE + ks + tig + 4]);
                af[im][3] = __float_as_uint(as[(r + 8) * CH_AS_STRIDE + ks + tig + 4]);
            }
#pragma unroll
            for (int in = 0; in < 4; in++) {
                int c = wn * 32 + in * 8 + gid;
                bf[in][0] = __float_as_uint(bs[(ks + tig) * CH_BS_STRIDE + c]);
                bf[in][1] = __float_as_uint(bs[(ks + tig + 4) * CH_BS_STRIDE + c]);
            }
#pragma unroll
            for (int im = 0; im < 4; im++)
#pragma unroll
                for (int in = 0; in < 4; in++)
                    mma_tf32(acc[im][in], af[im], bf[in]);
        }
        __syncthreads();
    }

#pragma unroll
    for (int im = 0; im < 4; im++) {
        int r0 = m0 + wm * 64 + im * 16 + gid;
#pragma unroll
        for (int in = 0; in < 4; in++) {
            int c0 = n0 + wn * 32 + in * 8 + 2 * tig;
            float2 v0 = make_float2(acc[im][in][0], acc[im][in][1]);
            *(float2*)(Cb + (size_t)r0 * NSEQ + c0) = v0;
            float2 v1 = make_float2(acc[im][in][2], acc[im][in][3]);
            *(float2*)(Cb + (size_t)(r0 + 8) * NSEQ + c0) = v1;
        }
    }
}

// ---------------- host ----------------
extern "C" void kernel_launch(void* const* d_in, const int* in_sizes, int n_in,
                              void* d_out, int out_size)
{
    const float* x     = (const float*)d_in[0];
    const float* adj   = (const float*)d_in[1];
    const float* Wf0   = (const float*)d_in[2];
    const float* Wq    = (const float*)d_in[3];
    const float* Wk    = (const float*)d_in[4];
    const float* Wv    = (const float*)d_in[5];
    const float* Wo    = (const float*)d_in[6];
    const float* gamma = (const float*)d_in[7];
    const float* beta  = (const float*)d_in[8];
    float* out_x    = (float*)d_out;
    float* out_attn = (float*)d_out + (size_t)BB * NSEQ * DD;

    float *X, *Q, *K, *V, *O, *T, *E, *RSI, *A0, *A1;
    unsigned* MB;
    cudaGetSymbolAddress((void**)&X, g_X);
    cudaGetSymbolAddress((void**)&Q, g_Q);
    cudaGetSymbolAddress((void**)&K, g_K);
    cudaGetSymbolAddress((void**)&V, g_V);
    cudaGetSymbolAddress((void**)&O, g_O);
    cudaGetSymbolAddress((void**)&T, g_T);
    cudaGetSymbolAddress((void**)&E, g_E);
    cudaGetSymbolAddress((void**)&RSI, g_RSI);
    cudaGetSymbolAddress((void**)&A0, g_A0);
    cudaGetSymbolAddress((void**)&A1, g_A1);
    cudaGetSymbolAddress((void**)&MB, g_MB);

    cudaFuncSetAttribute(k_pvagg, cudaFuncAttributeMaxDynamicSharedMemorySize, PVAGG_SMEM);
    cudaFuncSetAttribute(k_chain_tf32, cudaFuncAttributeMaxDynamicSharedMemorySize, CHAIN_SMEM);

    const int WSZ = 256 * 256;

    k_maskbits<<<512, 256>>>(adj, MB);
    k_proj<<<dim3(64, 4, 1), 256>>>(x, Wf0, Wf0, Wf0, X, X, X);

    for (int i = 0; i < 2; i++) {
        k_proj<<<dim3(64, 4, 3), 256>>>(X, Wq + i * WSZ, Wk + i * WSZ, Wv + i * WSZ, Q, K, V);
        k_scores<<<dim3(NSEQ / 32, BB * HH), 256>>>(Q, K, MB, E, RSI);
        k_pvagg<<<dim3(NSEQ / 32, BB), 512, PVAGG_SMEM>>>(E, RSI, V, O, (i == 0) ? A0 : A1);
        k_proj<<<dim3(64, 4, 1), 256>>>(O, Wo + i * WSZ, Wo + i * WSZ, Wo + i * WSZ, T, T, T);
        k_addln<<<BB * NSEQ, 256>>>(X, T, gamma + i * 256, beta + i * 256);
    }

    k_chain_tf32<<<dim3(NSEQ / 128, NSEQ / 128, BB), 256, CHAIN_SMEM>>>(A1, A0, out_attn);

    cudaMemcpyAsync(out_x, X, (size_t)BB * NSEQ * DD * sizeof(float),
                    cudaMemcpyDeviceToDevice);
}

// round 3
// speedup vs baseline: 2.8244x; 1.7856x over previous
#include <cuda_runtime.h>
#include <cuda_fp16.h>
#include <cstdint>

#define BB 2
#define NSEQ 2048
#define DD 256
#define HH 8
#define DH 32
#define SCALE 0.17677669529663687f  // 1/sqrt(32)

// ---------------- device scratch ----------------
__device__ float g_X[BB * NSEQ * DD];
__device__ float g_O[BB * NSEQ * DD];
__device__ float g_T[BB * NSEQ * DD];
__device__ __half g_Qh[BB * NSEQ * DD];
__device__ __half g_Kh[BB * NSEQ * DD];
__device__ __half g_Vh[BB * NSEQ * DD];
__device__ __half g_Eh[(size_t)BB * HH * NSEQ * NSEQ];   // exp(masked scores), unnormalized, half
__device__ float g_RSI[BB * HH * NSEQ];                  // reciprocal row sums
__device__ __half g_A0[(size_t)BB * NSEQ * NSEQ];        // head-avg attention layer0 (half)
__device__ __half g_A1[(size_t)BB * NSEQ * NSEQ];        // head-avg attention layer1 (half)
__device__ unsigned g_MB[NSEQ * (NSEQ / 32)];            // adjacency bitmask

// ---------------- asm helpers ----------------
__device__ __forceinline__ unsigned smem_u32(const void* p) {
    return (unsigned)__cvta_generic_to_shared(p);
}
__device__ __forceinline__ void cp16(unsigned dst, const void* src) {
    asm volatile("cp.async.cg.shared.global [%0], [%1], 16;" :: "r"(dst), "l"(src));
}
__device__ __forceinline__ void cp_commit() { asm volatile("cp.async.commit_group;"); }
__device__ __forceinline__ void cp_wait0() { asm volatile("cp.async.wait_group 0;" ::: "memory"); }
__device__ __forceinline__ void cp_wait1() { asm volatile("cp.async.wait_group 1;" ::: "memory"); }

__device__ __forceinline__ void ldm_x4(unsigned d[4], unsigned addr) {
    asm volatile("ldmatrix.sync.aligned.m8n8.x4.shared.b16 {%0,%1,%2,%3}, [%4];"
                 : "=r"(d[0]), "=r"(d[1]), "=r"(d[2]), "=r"(d[3]) : "r"(addr));
}
__device__ __forceinline__ void ldm_x4t(unsigned d[4], unsigned addr) {
    asm volatile("ldmatrix.sync.aligned.m8n8.x4.trans.shared.b16 {%0,%1,%2,%3}, [%4];"
                 : "=r"(d[0]), "=r"(d[1]), "=r"(d[2]), "=r"(d[3]) : "r"(addr));
}
__device__ __forceinline__ void mma_h(float d[4], const unsigned a[4], const unsigned b[2]) {
    asm volatile(
        "mma.sync.aligned.m16n8k16.row.col.f32.f16.f16.f32 "
        "{%0,%1,%2,%3}, {%4,%5,%6,%7}, {%8,%9}, {%0,%1,%2,%3};"
        : "+f"(d[0]), "+f"(d[1]), "+f"(d[2]), "+f"(d[3])
        : "r"(a[0]), "r"(a[1]), "r"(a[2]), "r"(a[3]), "r"(b[0]), "r"(b[1]));
}

// ---------------- adjacency -> bitmask ----------------
__global__ void k_maskbits(const float* __restrict__ adj, unsigned* __restrict__ mb) {
    int w = blockIdx.x * blockDim.x + threadIdx.x;
    if (w >= NSEQ * (NSEQ / 32)) return;
    int i = w >> 6;
    int c = w & 63;
    const float* row = adj + (size_t)i * NSEQ + c * 32;
    unsigned bits = 0;
#pragma unroll
    for (int t = 0; t < 32; t++) bits |= (row[t] > 0.0f) ? (1u << t) : 0u;
    mb[w] = bits;
}

// ---------------- projection GEMM: C[m,n] = sum_k A[m,k] * W[n,k] (NT) ----------------
// fp32 compute; optional fp32 output C*, optional half output H*.
__global__ __launch_bounds__(256) void k_proj(
    const float* __restrict__ A,
    const float* __restrict__ W0, const float* __restrict__ W1, const float* __restrict__ W2,
    float* __restrict__ C0, float* __restrict__ C1, float* __restrict__ C2,
    __half* __restrict__ H0, __half* __restrict__ H1, __half* __restrict__ H2)
{
    const float* W = (blockIdx.z == 0) ? W0 : ((blockIdx.z == 1) ? W1 : W2);
    float* C       = (blockIdx.z == 0) ? C0 : ((blockIdx.z == 1) ? C1 : C2);
    __half* Hc     = (blockIdx.z == 0) ? H0 : ((blockIdx.z == 1) ? H1 : H2);
    int m0 = blockIdx.x * 64;
    int n0 = blockIdx.y * 64;
    __shared__ float As[16][65];
    __shared__ float Bs[16][65];
    int t  = threadIdx.x;
    int lr = t >> 2;
    int lk = (t & 3) * 4;
    int ty = t >> 4;
    int tx = t & 15;
    float acc[4][4] = {};
    for (int k0 = 0; k0 < 256; k0 += 16) {
        float4 a = *(const float4*)(A + (size_t)(m0 + lr) * 256 + k0 + lk);
        float4 w = *(const float4*)(W + (size_t)(n0 + lr) * 256 + k0 + lk);
        __syncthreads();
        As[lk + 0][lr] = a.x; As[lk + 1][lr] = a.y; As[lk + 2][lr] = a.z; As[lk + 3][lr] = a.w;
        Bs[lk + 0][lr] = w.x; Bs[lk + 1][lr] = w.y; Bs[lk + 2][lr] = w.z; Bs[lk + 3][lr] = w.w;
        __syncthreads();
#pragma unroll
        for (int kk = 0; kk < 16; kk++) {
            float av[4], bv[4];
#pragma unroll
            for (int r = 0; r < 4; r++) av[r] = As[kk][ty + 16 * r];
#pragma unroll
            for (int c = 0; c < 4; c++) bv[c] = Bs[kk][tx + 16 * c];
#pragma unroll
            for (int r = 0; r < 4; r++)
#pragma unroll
                for (int c = 0; c < 4; c++) acc[r][c] += av[r] * bv[c];
        }
    }
#pragma unroll
    for (int r = 0; r < 4; r++)
#pragma unroll
        for (int c = 0; c < 4; c++) {
            size_t idx = (size_t)(m0 + ty + 16 * r) * 256 + n0 + tx + 16 * c;
            if (C)  C[idx]  = acc[r][c];
            if (Hc) Hc[idx] = __float2half_rn(acc[r][c]);
        }
}

// ---------------- scores via fp16 mma + mask + exp + rowsum -> E half ----------------
#define QS_STR 40
#define KS_STR 40
__global__ __launch_bounds__(256) void k_scores(
    const __half* __restrict__ Qh, const __half* __restrict__ Kh,
    const unsigned* __restrict__ mb,
    __half* __restrict__ Eh, float* __restrict__ RSI)
{
    __shared__ __half Qs[64 * QS_STR];
    __shared__ __half Ks[128 * KS_STR];
    __shared__ float red[64 * 2];

    int bh = blockIdx.y, b = bh >> 3, h = bh & 7;
    int i0 = blockIdx.x * 64;
    int t = threadIdx.x, lane = t & 31, warp = t >> 5;
    int wm = warp & 3, wn = warp >> 2;
    int gid = lane >> 2, tig = lane & 3;

    // Q tile: 64 rows x 32 halfs = 256 16B chunks, one per thread
    {
        int row = t >> 2, c = (t & 3) * 8;
        cp16(smem_u32(&Qs[row * QS_STR + c]),
             Qh + ((size_t)(b * NSEQ + i0 + row)) * DD + h * 32 + c);
    }
    cp_commit();

    // ldmatrix lane addressing
    int arow = wm * 16 + (lane & 7) + ((lane >> 3) & 1) * 8;   // A blocks: r0-7/k0, r8-15/k0, r0-7/k8, r8-15/k8
    int acol = (lane >> 4) * 8;
    unsigned aBase = smem_u32(&Qs[arow * QS_STR + acol]);
    // B (non-trans on Ks[n][k]): blocks: n0-7/k0, n0-7/k8, n8-15/k0, n8-15/k8
    int brow = (lane & 7) + ((lane >> 4) & 1) * 8;
    int bcol = ((lane >> 3) & 1) * 8;

    float sA = 0.f, sB = 0.f;
    int gi_a = i0 + wm * 16 + gid;
    int gi_b = gi_a + 8;

    for (int jc = 0; jc < 16; jc++) {
        int j0 = jc * 128;
#pragma unroll
        for (int l = 0; l < 2; l++) {
            int idx = t + 256 * l;
            int row = idx >> 2, c = (idx & 3) * 8;
            cp16(smem_u32(&Ks[row * KS_STR + c]),
                 Kh + ((size_t)(b * NSEQ + j0 + row)) * DD + h * 32 + c);
        }
        cp_commit();
        cp_wait0();
        __syncthreads();

        float acc[8][4] = {};
#pragma unroll
        for (int d0 = 0; d0 < 32; d0 += 16) {
            unsigned a[4];
            ldm_x4(a, aBase + d0 * 2);
#pragma unroll
            for (int p = 0; p < 4; p++) {
                unsigned bb[4];
                ldm_x4(bb, smem_u32(&Ks[(wn * 64 + p * 16 + brow) * KS_STR + bcol + d0]));
                mma_h(acc[2 * p],     a, &bb[0]);
                mma_h(acc[2 * p + 1], a, &bb[2]);
            }
        }

        const unsigned* mba = &mb[gi_a * 64];
        const unsigned* mbb = &mb[gi_b * 64];
#pragma unroll
        for (int in = 0; in < 8; in++) {
            int gj = j0 + wn * 64 + in * 8 + 2 * tig;
            unsigned wa = mba[gj >> 5], wb = mbb[gj >> 5];
            int sh = gj & 31;
            float e0 = ((wa >> sh) & 1u)       ? __expf(acc[in][0] * SCALE) : 0.f;
            float e1 = ((wa >> (sh + 1)) & 1u) ? __expf(acc[in][1] * SCALE) : 0.f;
            float e2 = ((wb >> sh) & 1u)       ? __expf(acc[in][2] * SCALE) : 0.f;
            float e3 = ((wb >> (sh + 1)) & 1u) ? __expf(acc[in][3] * SCALE) : 0.f;
            sA += e0 + e1;
            sB += e2 + e3;
            *(__half2*)(Eh + ((size_t)bh * NSEQ + gi_a) * NSEQ + gj) = __floats2half2_rn(e0, e1);
            *(__half2*)(Eh + ((size_t)bh * NSEQ + gi_b) * NSEQ + gj) = __floats2half2_rn(e2, e3);
        }
        __syncthreads();
    }

    sA += __shfl_xor_sync(0xffffffffu, sA, 1);
    sA += __shfl_xor_sync(0xffffffffu, sA, 2);
    sB += __shfl_xor_sync(0xffffffffu, sB, 1);
    sB += __shfl_xor_sync(0xffffffffu, sB, 2);
    if (tig == 0) {
        red[(wm * 16 + gid) * 2 + wn]     = sA;
        red[(wm * 16 + gid + 8) * 2 + wn] = sB;
    }
    __syncthreads();
    if (t < 64)
        RSI[bh * NSEQ + i0 + t] = 1.0f / (red[t * 2] + red[t * 2 + 1]);
}

// ---------------- fused PV (fp16 mma) + head-averaged attention (half out) ----------------
#define PV_ES_STR 72
#define PV_VS_STR 264
#define PV_ES_HALFS (256 * PV_ES_STR)
#define PV_VS_HALFS (64 * PV_VS_STR)
#define PVAGG_SMEM ((PV_ES_HALFS + PV_VS_HALFS) * 2 + 256 * 4)

__global__ __launch_bounds__(512) void k_pvagg(
    const __half* __restrict__ Eh, const float* __restrict__ RSI,
    const __half* __restrict__ Vh, float* __restrict__ O, __half* __restrict__ A)
{
    extern __shared__ __half smh[];
    __half* Es = smh;
    __half* Vs = smh + PV_ES_HALFS;
    float* ws = (float*)(Vs + PV_VS_HALFS);

    int b = blockIdx.y, i0 = blockIdx.x * 32;
    int t = threadIdx.x, lane = t & 31, warp = t >> 5;
    int h = warp >> 1, s = warp & 1;
    int gid = lane >> 2, tig = lane & 3;

    if (t < 256) ws[t] = RSI[(b * HH + (t >> 5)) * NSEQ + i0 + (t & 31)];

    // A-frag lanes (non-trans), B-frag lanes (trans)
    int arow = (lane & 7) + ((lane >> 3) & 1) * 8;
    int acol = (lane >> 4) * 8;
    int brow = (lane & 7) + ((lane >> 3) & 1) * 8;
    int bcol = (lane >> 4) * 8;
    int er0 = h * 32 + s * 16;

    int ai = t >> 4, aj = (t & 15) * 4;

    float acc[4][4] = {};

    for (int jt = 0; jt < 32; jt++) {
        int j0 = jt * 64;
#pragma unroll
        for (int l = 0; l < 4; l++) {
            int idx = t + 512 * l;
            int row = idx >> 3, c = (idx & 7) * 8;
            int eh = row >> 5, ei = row & 31;
            cp16(smem_u32(&Es[row * PV_ES_STR + c]),
                 Eh + ((size_t)(b * HH + eh) * NSEQ + i0 + ei) * NSEQ + j0 + c);
        }
#pragma unroll
        for (int l = 0; l < 4; l++) {
            int idx = t + 512 * l;
            int row = idx >> 5, c = (idx & 31) * 8;
            cp16(smem_u32(&Vs[row * PV_VS_STR + c]),
                 Vh + ((size_t)(b * NSEQ + j0 + row)) * DD + c);
        }
        cp_commit();
        cp_wait0();
        __syncthreads();

        // head-averaged attention tile
        {
            float a0 = 0, a1 = 0, a2 = 0, a3 = 0;
#pragma unroll
            for (int hh = 0; hh < 8; hh++) {
                float w = ws[hh * 32 + ai];
                float2 f0 = __half22float2(*(__half2*)&Es[(hh * 32 + ai) * PV_ES_STR + aj]);
                float2 f1 = __half22float2(*(__half2*)&Es[(hh * 32 + ai) * PV_ES_STR + aj + 2]);
                a0 += w * f0.x; a1 += w * f0.y; a2 += w * f1.x; a3 += w * f1.y;
            }
            __half2 o0 = __floats2half2_rn(a0 * 0.125f, a1 * 0.125f);
            __half2 o1 = __floats2half2_rn(a2 * 0.125f, a3 * 0.125f);
            uint2 pk;
            pk.x = *(unsigned*)&o0;
            pk.y = *(unsigned*)&o1;
            *(uint2*)(A + ((size_t)b * NSEQ + i0 + ai) * NSEQ + j0 + aj) = pk;
        }

        // PV fp16 mma
#pragma unroll
        for (int ks = 0; ks < 64; ks += 16) {
            unsigned a[4];
            ldm_x4(a, smem_u32(&Es[(er0 + arow) * PV_ES_STR + ks + acol]));
#pragma unroll
            for (int p = 0; p < 2; p++) {
                unsigned bb[4];
                ldm_x4t(bb, smem_u32(&Vs[(ks + brow) * PV_VS_STR + h * 32 + p * 16 + bcol]));
                mma_h(acc[2 * p],     a, &bb[0]);
                mma_h(acc[2 * p + 1], a, &bb[2]);
            }
        }
        __syncthreads();
    }

    int r0 = s * 16 + gid;
    float w0 = ws[h * 32 + r0];
    float w1 = ws[h * 32 + r0 + 8];
#pragma unroll
    for (int in = 0; in < 4; in++) {
        int c0 = h * 32 + in * 8 + 2 * tig;
        size_t base = ((size_t)(b * NSEQ + i0 + r0)) * DD + c0;
        *(float2*)(O + base)          = make_float2(acc[in][0] * w0, acc[in][1] * w0);
        *(float2*)(O + base + 8 * DD) = make_float2(acc[in][2] * w1, acc[in][3] * w1);
    }
}

// ---------------- residual + layernorm (in place on X) ----------------
__global__ void k_addln(float* __restrict__ X, const float* __restrict__ T,
                        const float* __restrict__ g, const float* __restrict__ bta)
{
    int row = blockIdx.x;
    int t = threadIdx.x;
    float v = X[row * 256 + t] + T[row * 256 + t];
    float s = v, s2 = v * v;
#pragma unroll
    for (int off = 16; off > 0; off >>= 1) {
        s  += __shfl_xor_sync(0xffffffffu, s, off);
        s2 += __shfl_xor_sync(0xffffffffu, s2, off);
    }
    __shared__ float red[16];
    __shared__ float mu_s, rstd_s;
    int w = t >> 5, lane = t & 31;
    if (lane == 0) { red[w] = s; red[8 + w] = s2; }
    __syncthreads();
    if (t == 0) {
        float S = 0.f, S2 = 0.f;
#pragma unroll
        for (int i = 0; i < 8; i++) { S += red[i]; S2 += red[8 + i]; }
        float mu = S * (1.0f / 256.0f);
        float var = S2 * (1.0f / 256.0f) - mu * mu;
        mu_s = mu;
        rstd_s = rsqrtf(var + 1e-5f);
    }
    __syncthreads();
    X[row * 256 + t] = (v - mu_s) * rstd_s * g[t] + bta[t];
}

// ---------------- chain GEMM via fp16 mma, cp.async double-buffered ----------------
#define CH_AS_STR 72
#define CH_BS_STR 136
#define CH_AS_HALFS (128 * CH_AS_STR)
#define CH_BS_HALFS (64 * CH_BS_STR)
#define CHAIN_SMEM ((2 * CH_AS_HALFS + 2 * CH_BS_HALFS) * 2)

__global__ __launch_bounds__(256, 2) void k_chain_h(
    const __half* __restrict__ A, const __half* __restrict__ B, float* __restrict__ C)
{
    extern __shared__ __half chs[];
    __half* AsB = chs;
    __half* BsB = chs + 2 * CH_AS_HALFS;

    int bb = blockIdx.z;
    const __half* Ab = A + (size_t)bb * NSEQ * NSEQ;
    const __half* Bb = B + (size_t)bb * NSEQ * NSEQ;
    float* Cb = C + (size_t)bb * NSEQ * NSEQ;

    int t = threadIdx.x, lane = t & 31, warp = t >> 5;
    int wm = warp >> 2, wn = warp & 3;
    int gid = lane >> 2, tig = lane & 3;
    int m0 = blockIdx.y * 128, n0 = blockIdx.x * 128;

    int arow = (lane & 7) + ((lane >> 3) & 1) * 8;
    int acol = (lane >> 4) * 8;
    int brow = (lane & 7) + ((lane >> 3) & 1) * 8;
    int bcol = (lane >> 4) * 8;

    float acc[4][4][4] = {};

    auto issue = [&](int buf, int k0) {
        __half* as = AsB + buf * CH_AS_HALFS;
        __half* bs = BsB + buf * CH_BS_HALFS;
#pragma unroll
        for (int l = 0; l < 4; l++) {
            int idx = t + 256 * l;
            int r = idx >> 3, c = (idx & 7) * 8;
            cp16(smem_u32(&as[r * CH_AS_STR + c]), Ab + (size_t)(m0 + r) * NSEQ + k0 + c);
        }
#pragma unroll
        for (int l = 0; l < 4; l++) {
            int idx = t + 256 * l;
            int r = idx >> 4, c = (idx & 15) * 8;
            cp16(smem_u32(&bs[r * CH_BS_STR + c]), Bb + (size_t)(k0 + r) * NSEQ + n0 + c);
        }
        cp_commit();
    };

    issue(0, 0);
    for (int kt = 0; kt < 32; kt++) {
        int buf = kt & 1;
        if (kt + 1 < 32) {
            issue(buf ^ 1, (kt + 1) * 64);
            cp_wait1();
        } else {
            cp_wait0();
        }
        __syncthreads();

        __half* as = AsB + buf * CH_AS_HALFS;
        __half* bs = BsB + buf * CH_BS_HALFS;
#pragma unroll
        for (int ks = 0; ks < 64; ks += 16) {
            unsigned af[4][4], bf[2][4];
#pragma unroll
            for (int im = 0; im < 4; im++)
                ldm_x4(af[im], smem_u32(&as[(wm * 64 + im * 16 + arow) * CH_AS_STR + ks + acol]));
#pragma unroll
            for (int p = 0; p < 2; p++)
                ldm_x4t(bf[p], smem_u32(&bs[(ks + brow) * CH_BS_STR + wn * 32 + p * 16 + bcol]));
#pragma unroll
            for (int im = 0; im < 4; im++) {
                mma_h(acc[im][0], af[im], &bf[0][0]);
                mma_h(acc[im][1], af[im], &bf[0][2]);
                mma_h(acc[im][2], af[im], &bf[1][0]);
                mma_h(acc[im][3], af[im], &bf[1][2]);
            }
        }
        __syncthreads();
    }

#pragma unroll
    for (int im = 0; im < 4; im++) {
        int r0 = m0 + wm * 64 + im * 16 + gid;
#pragma unroll
        for (int in = 0; in < 4; in++) {
            int c0 = n0 + wn * 32 + in * 8 + 2 * tig;
            *(float2*)(Cb + (size_t)r0 * NSEQ + c0)       = make_float2(acc[im][in][0], acc[im][in][1]);
            *(float2*)(Cb + (size_t)(r0 + 8) * NSEQ + c0) = make_float2(acc[im][in][2], acc[im][in][3]);
        }
    }
}

// ---------------- host ----------------
extern "C" void kernel_launch(void* const* d_in, const int* in_sizes, int n_in,
                              void* d_out, int out_size)
{
    const float* x     = (const float*)d_in[0];
    const float* adj   = (const float*)d_in[1];
    const float* Wf0   = (const float*)d_in[2];
    const float* Wq    = (const float*)d_in[3];
    const float* Wk    = (const float*)d_in[4];
    const float* Wv    = (const float*)d_in[5];
    const float* Wo    = (const float*)d_in[6];
    const float* gamma = (const float*)d_in[7];
    const float* beta  = (const float*)d_in[8];
    float* out_x    = (float*)d_out;
    float* out_attn = (float*)d_out + (size_t)BB * NSEQ * DD;

    float *X, *O, *T, *RSI;
    __half *Qh, *Kh, *Vh, *Eh, *A0, *A1;
    unsigned* MB;
    cudaGetSymbolAddress((void**)&X, g_X);
    cudaGetSymbolAddress((void**)&O, g_O);
    cudaGetSymbolAddress((void**)&T, g_T);
    cudaGetSymbolAddress((void**)&Qh, g_Qh);
    cudaGetSymbolAddress((void**)&Kh, g_Kh);
    cudaGetSymbolAddress((void**)&Vh, g_Vh);
    cudaGetSymbolAddress((void**)&Eh, g_Eh);
    cudaGetSymbolAddress((void**)&RSI, g_RSI);
    cudaGetSymbolAddress((void**)&A0, g_A0);
    cudaGetSymbolAddress((void**)&A1, g_A1);
    cudaGetSymbolAddress((void**)&MB, g_MB);

    cudaFuncSetAttribute(k_pvagg, cudaFuncAttributeMaxDynamicSharedMemorySize, PVAGG_SMEM);
    cudaFuncSetAttribute(k_chain_h, cudaFuncAttributeMaxDynamicSharedMemorySize, CHAIN_SMEM);

    const int WSZ = 256 * 256;

    k_maskbits<<<512, 256>>>(adj, MB);
    k_proj<<<dim3(64, 4, 1), 256>>>(x, Wf0, Wf0, Wf0, X, X, X,
                                    (half*)nullptr, (half*)nullptr, (half*)nullptr);

    for (int i = 0; i < 2; i++) {
        // QKV projections -> half outputs only
        k_proj<<<dim3(64, 4, 3), 256>>>(X, Wq + i * WSZ, Wk + i * WSZ, Wv + i * WSZ,
                                        (float*)nullptr, (float*)nullptr, (float*)nullptr,
                                        Qh, Kh, Vh);
        k_scores<<<dim3(NSEQ / 64, BB * HH), 256>>>(Qh, Kh, MB, Eh, RSI);
        k_pvagg<<<dim3(NSEQ / 32, BB), 512, PVAGG_SMEM>>>(Eh, RSI, Vh, O, (i == 0) ? A0 : A1);
        k_proj<<<dim3(64, 4, 1), 256>>>(O, Wo + i * WSZ, Wo + i * WSZ, Wo + i * WSZ, T, T, T,
                                        (half*)nullptr, (half*)nullptr, (half*)nullptr);
        k_addln<<<BB * NSEQ, 256>>>(X, T, gamma + i * 256, beta + i * 256);
    }

    k_chain_h<<<dim3(NSEQ / 128, NSEQ / 128, BB), 256, CHAIN_SMEM>>>(A1, A0, out_attn);

    cudaMemcpyAsync(out_x, X, (size_t)BB * NSEQ * DD * sizeof(float),
                    cudaMemcpyDeviceToDevice);
}

// round 4
// speedup vs baseline: 3.8751x; 1.3720x over previous
#include <cuda_runtime.h>
#include <cuda_fp16.h>
#include <cstdint>

#define BB 2
#define NSEQ 2048
#define DD 256
#define HH 8
#define DH 32
#define SCALE 0.17677669529663687f  // 1/sqrt(32)

// ---------------- device scratch ----------------
__device__ float g_X[BB * NSEQ * DD];
__device__ float g_T[BB * NSEQ * DD];
__device__ __half g_Xh[BB * NSEQ * DD];
__device__ __half g_Oh[BB * NSEQ * DD];
__device__ __half g_Qh[BB * NSEQ * DD];
__device__ __half g_Kh[BB * NSEQ * DD];
__device__ __half g_Vh[BB * NSEQ * DD];
__device__ __half g_Eh[(size_t)BB * HH * NSEQ * NSEQ];   // exp(masked scores), unnormalized, half
__device__ float g_RSI[BB * HH * NSEQ];                  // reciprocal row sums
__device__ __half g_A0[(size_t)BB * NSEQ * NSEQ];        // head-avg attention layer0 (half)
__device__ __half g_A1[(size_t)BB * NSEQ * NSEQ];        // head-avg attention layer1 (half)
__device__ unsigned g_MB[NSEQ * (NSEQ / 32)];            // adjacency bitmask
__device__ __half g_Wqh[2 * 256 * 256];
__device__ __half g_Wkh[2 * 256 * 256];
__device__ __half g_Wvh[2 * 256 * 256];
__device__ __half g_Woh[2 * 256 * 256];

// ---------------- asm helpers ----------------
__device__ __forceinline__ unsigned smem_u32(const void* p) {
    return (unsigned)__cvta_generic_to_shared(p);
}
__device__ __forceinline__ void cp16(unsigned dst, const void* src) {
    asm volatile("cp.async.cg.shared.global [%0], [%1], 16;" :: "r"(dst), "l"(src));
}
__device__ __forceinline__ void cp_commit() { asm volatile("cp.async.commit_group;"); }
__device__ __forceinline__ void cp_wait0() { asm volatile("cp.async.wait_group 0;" ::: "memory"); }
__device__ __forceinline__ void cp_wait1() { asm volatile("cp.async.wait_group 1;" ::: "memory"); }

__device__ __forceinline__ void ldm_x4(unsigned d[4], unsigned addr) {
    asm volatile("ldmatrix.sync.aligned.m8n8.x4.shared.b16 {%0,%1,%2,%3}, [%4];"
                 : "=r"(d[0]), "=r"(d[1]), "=r"(d[2]), "=r"(d[3]) : "r"(addr));
}
__device__ __forceinline__ void ldm_x4t(unsigned d[4], unsigned addr) {
    asm volatile("ldmatrix.sync.aligned.m8n8.x4.trans.shared.b16 {%0,%1,%2,%3}, [%4];"
                 : "=r"(d[0]), "=r"(d[1]), "=r"(d[2]), "=r"(d[3]) : "r"(addr));
}
__device__ __forceinline__ void mma_h(float d[4], const unsigned a[4], const unsigned b[2]) {
    asm volatile(
        "mma.sync.aligned.m16n8k16.row.col.f32.f16.f16.f32 "
        "{%0,%1,%2,%3}, {%4,%5,%6,%7}, {%8,%9}, {%0,%1,%2,%3};"
        : "+f"(d[0]), "+f"(d[1]), "+f"(d[2]), "+f"(d[3])
        : "r"(a[0]), "r"(a[1]), "r"(a[2]), "r"(a[3]), "r"(b[0]), "r"(b[1]));
}

// ---------------- float -> half conversion ----------------
__global__ void k_f2h(const float* __restrict__ s, __half* __restrict__ d, int n4) {
    int i = blockIdx.x * blockDim.x + threadIdx.x;
    if (i >= n4) return;
    float4 v = *(const float4*)(s + i * 4);
    __half2 a = __floats2half2_rn(v.x, v.y);
    __half2 b = __floats2half2_rn(v.z, v.w);
    uint2 pk;
    pk.x = *(unsigned*)&a;
    pk.y = *(unsigned*)&b;
    *(uint2*)(d + i * 4) = pk;
}

// ---------------- adjacency -> bitmask ----------------
__global__ void k_maskbits(const float* __restrict__ adj, unsigned* __restrict__ mb) {
    int w = blockIdx.x * blockDim.x + threadIdx.x;
    if (w >= NSEQ * (NSEQ / 32)) return;
    int i = w >> 6;
    int c = w & 63;
    const float* row = adj + (size_t)i * NSEQ + c * 32;
    unsigned bits = 0;
#pragma unroll
    for (int t = 0; t < 32; t++) bits |= (row[t] > 0.0f) ? (1u << t) : 0u;
    mb[w] = bits;
}

// ---------------- fp32 projection (only for Wf0): C/H[m,n] = sum_k A[m,k]*W[n,k] ----------------
__global__ __launch_bounds__(256) void k_proj(
    const float* __restrict__ A, const float* __restrict__ W,
    float* __restrict__ C, __half* __restrict__ Hc)
{
    int m0 = blockIdx.x * 64;
    int n0 = blockIdx.y * 64;
    __shared__ float As[16][65];
    __shared__ float Bs[16][65];
    int t  = threadIdx.x;
    int lr = t >> 2;
    int lk = (t & 3) * 4;
    int ty = t >> 4;
    int tx = t & 15;
    float acc[4][4] = {};
    for (int k0 = 0; k0 < 256; k0 += 16) {
        float4 a = *(const float4*)(A + (size_t)(m0 + lr) * 256 + k0 + lk);
        float4 w = *(const float4*)(W + (size_t)(n0 + lr) * 256 + k0 + lk);
        __syncthreads();
        As[lk + 0][lr] = a.x; As[lk + 1][lr] = a.y; As[lk + 2][lr] = a.z; As[lk + 3][lr] = a.w;
        Bs[lk + 0][lr] = w.x; Bs[lk + 1][lr] = w.y; Bs[lk + 2][lr] = w.z; Bs[lk + 3][lr] = w.w;
        __syncthreads();
#pragma unroll
        for (int kk = 0; kk < 16; kk++) {
            float av[4], bv[4];
#pragma unroll
            for (int r = 0; r < 4; r++) av[r] = As[kk][ty + 16 * r];
#pragma unroll
            for (int c = 0; c < 4; c++) bv[c] = Bs[kk][tx + 16 * c];
#pragma unroll
            for (int r = 0; r < 4; r++)
#pragma unroll
                for (int c = 0; c < 4; c++) acc[r][c] += av[r] * bv[c];
        }
    }
#pragma unroll
    for (int r = 0; r < 4; r++)
#pragma unroll
        for (int c = 0; c < 4; c++) {
            size_t idx = (size_t)(m0 + ty + 16 * r) * 256 + n0 + tx + 16 * c;
            C[idx]  = acc[r][c];
            Hc[idx] = __float2half_rn(acc[r][c]);
        }
}

// ---------------- fp16 tensor-core projection: out[m,n] = sum_k Xh[m,k]*Wh[n,k] ----------------
// grid (32, 4, nz); block 256. z selects weight/output.
#define PJ_STR 40
__global__ __launch_bounds__(256) void k_projh(
    const __half* __restrict__ Xin,
    const __half* __restrict__ W0, const __half* __restrict__ W1, const __half* __restrict__ W2,
    __half* __restrict__ H0, __half* __restrict__ H1, __half* __restrict__ H2,
    float* __restrict__ Fout)
{
    const __half* W = (blockIdx.z == 0) ? W0 : ((blockIdx.z == 1) ? W1 : W2);
    __half* Hc      = (blockIdx.z == 0) ? H0 : ((blockIdx.z == 1) ? H1 : H2);

    __shared__ __half Xs[2][128 * PJ_STR];
    __shared__ __half Ws[2][64 * PJ_STR];

    int m0 = blockIdx.x * 128, n0 = blockIdx.y * 64;
    int t = threadIdx.x, lane = t & 31, warp = t >> 5;
    int wm = warp >> 1, wn = warp & 1;
    int gid = lane >> 2, tig = lane & 3;

    int arow = (lane & 7) + ((lane >> 3) & 1) * 8;
    int acol = (lane >> 4) * 8;
    int brow = (lane & 7) + ((lane >> 4) & 1) * 8;
    int bcol = ((lane >> 3) & 1) * 8;

    float acc[2][4][4] = {};

    auto issue = [&](int buf, int k0) {
#pragma unroll
        for (int l = 0; l < 2; l++) {
            int idx = t + 256 * l;
            int r = idx >> 2, c = (idx & 3) * 8;
            cp16(smem_u32(&Xs[buf][r * PJ_STR + c]), Xin + (size_t)(m0 + r) * DD + k0 + c);
        }
        {
            int r = t >> 2, c = (t & 3) * 8;
            cp16(smem_u32(&Ws[buf][r * PJ_STR + c]), W + (size_t)(n0 + r) * DD + k0 + c);
        }
        cp_commit();
    };

    issue(0, 0);
    for (int kt = 0; kt < 8; kt++) {
        int buf = kt & 1;
        if (kt + 1 < 8) { issue(buf ^ 1, (kt + 1) * 32); cp_wait1(); }
        else cp_wait0();
        __syncthreads();

#pragma unroll
        for (int ks = 0; ks < 32; ks += 16) {
            unsigned af[2][4], bf[2][4];
#pragma unroll
            for (int im = 0; im < 2; im++)
                ldm_x4(af[im], smem_u32(&Xs[buf][(wm * 32 + im * 16 + arow) * PJ_STR + ks + acol]));
#pragma unroll
            for (int p = 0; p < 2; p++)
                ldm_x4(bf[p], smem_u32(&Ws[buf][(wn * 32 + p * 16 + brow) * PJ_STR + ks + bcol]));
#pragma unroll
            for (int im = 0; im < 2; im++) {
                mma_h(acc[im][0], af[im], &bf[0][0]);
                mma_h(acc[im][1], af[im], &bf[0][2]);
                mma_h(acc[im][2], af[im], &bf[1][0]);
                mma_h(acc[im][3], af[im], &bf[1][2]);
            }
        }
        __syncthreads();
    }

#pragma unroll
    for (int im = 0; im < 2; im++) {
        int r0 = m0 + wm * 32 + im * 16 + gid;
#pragma unroll
        for (int in = 0; in < 4; in++) {
            int c0 = n0 + wn * 32 + in * 8 + 2 * tig;
            if (Hc) {
                __half2 h0 = __floats2half2_rn(acc[im][in][0], acc[im][in][1]);
                __half2 h1 = __floats2half2_rn(acc[im][in][2], acc[im][in][3]);
                *(__half2*)(Hc + (size_t)r0 * DD + c0)       = h0;
                *(__half2*)(Hc + (size_t)(r0 + 8) * DD + c0) = h1;
            }
            if (Fout) {
                *(float2*)(Fout + (size_t)r0 * DD + c0)       = make_float2(acc[im][in][0], acc[im][in][1]);
                *(float2*)(Fout + (size_t)(r0 + 8) * DD + c0) = make_float2(acc[im][in][2], acc[im][in][3]);
            }
        }
    }
}

// ---------------- scores via fp16 mma + mask + exp + rowsum -> E half (smem-staged store) ----------------
#define QS_STR 40
#define KS_STR 40
#define ES_STR 136
__global__ __launch_bounds__(256) void k_scores(
    const __half* __restrict__ Qh, const __half* __restrict__ Kh,
    const unsigned* __restrict__ mb,
    __half* __restrict__ Eh, float* __restrict__ RSI)
{
    __shared__ __half Qs[64 * QS_STR];
    __shared__ __half Ks[128 * KS_STR];
    __shared__ __half Es[64 * ES_STR];
    __shared__ float red[64 * 2];

    int bh = blockIdx.y, b = bh >> 3, h = bh & 7;
    int i0 = blockIdx.x * 64;
    int t = threadIdx.x, lane = t & 31, warp = t >> 5;
    int wm = warp & 3, wn = warp >> 2;
    int gid = lane >> 2, tig = lane & 3;

    {
        int row = t >> 2, c = (t & 3) * 8;
        cp16(smem_u32(&Qs[row * QS_STR + c]),
             Qh + ((size_t)(b * NSEQ + i0 + row)) * DD + h * 32 + c);
    }
    cp_commit();

    int arow = wm * 16 + (lane & 7) + ((lane >> 3) & 1) * 8;
    int acol = (lane >> 4) * 8;
    unsigned aBase = smem_u32(&Qs[arow * QS_STR + acol]);
    int brow = (lane & 7) + ((lane >> 4) & 1) * 8;
    int bcol = ((lane >> 3) & 1) * 8;

    float sA = 0.f, sB = 0.f;
    int gi_a = i0 + wm * 16 + gid;
    int gi_b = gi_a + 8;
    int lrowA = wm * 16 + gid;

    for (int jc = 0; jc < 16; jc++) {
        int j0 = jc * 128;
#pragma unroll
        for (int l = 0; l < 2; l++) {
            int idx = t + 256 * l;
            int row = idx >> 2, c = (idx & 3) * 8;
            cp16(smem_u32(&Ks[row * KS_STR + c]),
                 Kh + ((size_t)(b * NSEQ + j0 + row)) * DD + h * 32 + c);
        }
        cp_commit();
        cp_wait0();
        __syncthreads();

        float acc[8][4] = {};
#pragma unroll
        for (int d0 = 0; d0 < 32; d0 += 16) {
            unsigned a[4];
            ldm_x4(a, aBase + d0 * 2);
#pragma unroll
            for (int p = 0; p < 4; p++) {
                unsigned bb[4];
                ldm_x4(bb, smem_u32(&Ks[(wn * 64 + p * 16 + brow) * KS_STR + bcol + d0]));
                mma_h(acc[2 * p],     a, &bb[0]);
                mma_h(acc[2 * p + 1], a, &bb[2]);
            }
        }

        const unsigned* mba = &mb[gi_a * 64];
        const unsigned* mbb = &mb[gi_b * 64];
#pragma unroll
        for (int in = 0; in < 8; in++) {
            int col = wn * 64 + in * 8 + 2 * tig;
            int gj = j0 + col;
            unsigned wa = mba[gj >> 5], wb = mbb[gj >> 5];
            int sh = gj & 31;
            float e0 = ((wa >> sh) & 1u)       ? __expf(acc[in][0] * SCALE) : 0.f;
            float e1 = ((wa >> (sh + 1)) & 1u) ? __expf(acc[in][1] * SCALE) : 0.f;
            float e2 = ((wb >> sh) & 1u)       ? __expf(acc[in][2] * SCALE) : 0.f;
            float e3 = ((wb >> (sh + 1)) & 1u) ? __expf(acc[in][3] * SCALE) : 0.f;
            sA += e0 + e1;
            sB += e2 + e3;
            *(__half2*)&Es[lrowA * ES_STR + col]       = __floats2half2_rn(e0, e1);
            *(__half2*)&Es[(lrowA + 8) * ES_STR + col] = __floats2half2_rn(e2, e3);
        }
        __syncthreads();
        // coalesced copy-out: 64 rows x 128 halfs = 1024 x 16B
#pragma unroll
        for (int l = 0; l < 4; l++) {
            int id = t + 256 * l;
            int row = id >> 4, cc = (id & 15) * 8;
            uint4 v = *(uint4*)&Es[row * ES_STR + cc];
            *(uint4*)(Eh + ((size_t)bh * NSEQ + i0 + row) * NSEQ + j0 + cc) = v;
        }
        __syncthreads();
    }

    sA += __shfl_xor_sync(0xffffffffu, sA, 1);
    sA += __shfl_xor_sync(0xffffffffu, sA, 2);
    sB += __shfl_xor_sync(0xffffffffu, sB, 1);
    sB += __shfl_xor_sync(0xffffffffu, sB, 2);
    if (tig == 0) {
        red[(wm * 16 + gid) * 2 + wn]     = sA;
        red[(wm * 16 + gid + 8) * 2 + wn] = sB;
    }
    __syncthreads();
    if (t < 64)
        RSI[bh * NSEQ + i0 + t] = 1.0f / (red[t * 2] + red[t * 2 + 1]);
}

// ---------------- fused PV (fp16 mma) + head-averaged attention (half out) ----------------
#define PV_ES_STR 72
#define PV_VS_STR 264
#define PV_ES_HALFS (256 * PV_ES_STR)
#define PV_VS_HALFS (64 * PV_VS_STR)
#define PVAGG_SMEM ((PV_ES_HALFS + PV_VS_HALFS) * 2 + 256 * 4)

__global__ __launch_bounds__(512) void k_pvagg(
    const __half* __restrict__ Eh, const float* __restrict__ RSI,
    const __half* __restrict__ Vh, __half* __restrict__ Oh, __half* __restrict__ A)
{
    extern __shared__ __half smh[];
    __half* Es = smh;
    __half* Vs = smh + PV_ES_HALFS;
    float* ws = (float*)(Vs + PV_VS_HALFS);

    int b = blockIdx.y, i0 = blockIdx.x * 32;
    int t = threadIdx.x, lane = t & 31, warp = t >> 5;
    int h = warp >> 1, s = warp & 1;
    int gid = lane >> 2, tig = lane & 3;

    if (t < 256) ws[t] = RSI[(b * HH + (t >> 5)) * NSEQ + i0 + (t & 31)];

    int arow = (lane & 7) + ((lane >> 3) & 1) * 8;
    int acol = (lane >> 4) * 8;
    int brow = (lane & 7) + ((lane >> 3) & 1) * 8;
    int bcol = (lane >> 4) * 8;
    int er0 = h * 32 + s * 16;

    int ai = t >> 4, aj = (t & 15) * 4;

    float acc[4][4] = {};

    for (int jt = 0; jt < 32; jt++) {
        int j0 = jt * 64;
#pragma unroll
        for (int l = 0; l < 4; l++) {
            int idx = t + 512 * l;
            int row = idx >> 3, c = (idx & 7) * 8;
            int eh = row >> 5, ei = row & 31;
            cp16(smem_u32(&Es[row * PV_ES_STR + c]),
                 Eh + ((size_t)(b * HH + eh) * NSEQ + i0 + ei) * NSEQ + j0 + c);
        }
#pragma unroll
        for (int l = 0; l < 4; l++) {
            int idx = t + 512 * l;
            int row = idx >> 5, c = (idx & 31) * 8;
            cp16(smem_u32(&Vs[row * PV_VS_STR + c]),
                 Vh + ((size_t)(b * NSEQ + j0 + row)) * DD + c);
        }
        cp_commit();
        cp_wait0();
        __syncthreads();

        {
            float a0 = 0, a1 = 0, a2 = 0, a3 = 0;
#pragma unroll
            for (int hh = 0; hh < 8; hh++) {
                float w = ws[hh * 32 + ai];
                float2 f0 = __half22float2(*(__half2*)&Es[(hh * 32 + ai) * PV_ES_STR + aj]);
                float2 f1 = __half22float2(*(__half2*)&Es[(hh * 32 + ai) * PV_ES_STR + aj + 2]);
                a0 += w * f0.x; a1 += w * f0.y; a2 += w * f1.x; a3 += w * f1.y;
            }
            __half2 o0 = __floats2half2_rn(a0 * 0.125f, a1 * 0.125f);
            __half2 o1 = __floats2half2_rn(a2 * 0.125f, a3 * 0.125f);
            uint2 pk;
            pk.x = *(unsigned*)&o0;
            pk.y = *(unsigned*)&o1;
            *(uint2*)(A + ((size_t)b * NSEQ + i0 + ai) * NSEQ + j0 + aj) = pk;
        }

#pragma unroll
        for (int ks = 0; ks < 64; ks += 16) {
            unsigned a[4];
            ldm_x4(a, smem_u32(&Es[(er0 + arow) * PV_ES_STR + ks + acol]));
#pragma unroll
            for (int p = 0; p < 2; p++) {
                unsigned bb[4];
                ldm_x4t(bb, smem_u32(&Vs[(ks + brow) * PV_VS_STR + h * 32 + p * 16 + bcol]));
                mma_h(acc[2 * p],     a, &bb[0]);
                mma_h(acc[2 * p + 1], a, &bb[2]);
            }
        }
        __syncthreads();
    }

    int r0 = s * 16 + gid;
    float w0 = ws[h * 32 + r0];
    float w1 = ws[h * 32 + r0 + 8];
#pragma unroll
    for (int in = 0; in < 4; in++) {
        int c0 = h * 32 + in * 8 + 2 * tig;
        size_t base = ((size_t)(b * NSEQ + i0 + r0)) * DD + c0;
        *(__half2*)(Oh + base)          = __floats2half2_rn(acc[in][0] * w0, acc[in][1] * w0);
        *(__half2*)(Oh + base + 8 * DD) = __floats2half2_rn(acc[in][2] * w1, acc[in][3] * w1);
    }
}

// ---------------- residual + layernorm (in place on X, mirrors to Xh) ----------------
__global__ void k_addln(float* __restrict__ X, __half* __restrict__ Xh,
                        const float* __restrict__ T,
                        const float* __restrict__ g, const float* __restrict__ bta)
{
    int row = blockIdx.x;
    int t = threadIdx.x;
    float v = X[row * 256 + t] + T[row * 256 + t];
    float s = v, s2 = v * v;
#pragma unroll
    for (int off = 16; off > 0; off >>= 1) {
        s  += __shfl_xor_sync(0xffffffffu, s, off);
        s2 += __shfl_xor_sync(0xffffffffu, s2, off);
    }
    __shared__ float red[16];
    __shared__ float mu_s, rstd_s;
    int w = t >> 5, lane = t & 31;
    if (lane == 0) { red[w] = s; red[8 + w] = s2; }
    __syncthreads();
    if (t == 0) {
        float S = 0.f, S2 = 0.f;
#pragma unroll
        for (int i = 0; i < 8; i++) { S += red[i]; S2 += red[8 + i]; }
        float mu = S * (1.0f / 256.0f);
        float var = S2 * (1.0f / 256.0f) - mu * mu;
        mu_s = mu;
        rstd_s = rsqrtf(var + 1e-5f);
    }
    __syncthreads();
    float r = (v - mu_s) * rstd_s * g[t] + bta[t];
    X[row * 256 + t] = r;
    Xh[row * 256 + t] = __float2half_rn(r);
}

// ---------------- chain GEMM via fp16 mma, cp.async double-buffered ----------------
#define CH_AS_STR 72
#define CH_BS_STR 136
#define CH_AS_HALFS (128 * CH_AS_STR)
#define CH_BS_HALFS (64 * CH_BS_STR)
#define CHAIN_SMEM ((2 * CH_AS_HALFS + 2 * CH_BS_HALFS) * 2)

__global__ __launch_bounds__(256, 2) void k_chain_h(
    const __half* __restrict__ A, const __half* __restrict__ B, float* __restrict__ C)
{
    extern __shared__ __half chs[];
    __half* AsB = chs;
    __half* BsB = chs + 2 * CH_AS_HALFS;

    int bb = blockIdx.z;
    const __half* Ab = A + (size_t)bb * NSEQ * NSEQ;
    const __half* Bb = B + (size_t)bb * NSEQ * NSEQ;
    float* Cb = C + (size_t)bb * NSEQ * NSEQ;

    int t = threadIdx.x, lane = t & 31, warp = t >> 5;
    int wm = warp >> 2, wn = warp & 3;
    int gid = lane >> 2, tig = lane & 3;
    int m0 = blockIdx.y * 128, n0 = blockIdx.x * 128;

    int arow = (lane & 7) + ((lane >> 3) & 1) * 8;
    int acol = (lane >> 4) * 8;
    int brow = (lane & 7) + ((lane >> 3) & 1) * 8;
    int bcol = (lane >> 4) * 8;

    float acc[4][4][4] = {};

    auto issue = [&](int buf, int k0) {
        __half* as = AsB + buf * CH_AS_HALFS;
        __half* bs = BsB + buf * CH_BS_HALFS;
#pragma unroll
        for (int l = 0; l < 4; l++) {
            int idx = t + 256 * l;
            int r = idx >> 3, c = (idx & 7) * 8;
            cp16(smem_u32(&as[r * CH_AS_STR + c]), Ab + (size_t)(m0 + r) * NSEQ + k0 + c);
        }
#pragma unroll
        for (int l = 0; l < 4; l++) {
            int idx = t + 256 * l;
            int r = idx >> 4, c = (idx & 15) * 8;
            cp16(smem_u32(&bs[r * CH_BS_STR + c]), Bb + (size_t)(k0 + r) * NSEQ + n0 + c);
        }
        cp_commit();
    };

    issue(0, 0);
    for (int kt = 0; kt < 32; kt++) {
        int buf = kt & 1;
        if (kt + 1 < 32) {
            issue(buf ^ 1, (kt + 1) * 64);
            cp_wait1();
        } else {
            cp_wait0();
        }
        __syncthreads();

        __half* as = AsB + buf * CH_AS_HALFS;
        __half* bs = BsB + buf * CH_BS_HALFS;
#pragma unroll
        for (int ks = 0; ks < 64; ks += 16) {
            unsigned af[4][4], bf[2][4];
#pragma unroll
            for (int im = 0; im < 4; im++)
                ldm_x4(af[im], smem_u32(&as[(wm * 64 + im * 16 + arow) * CH_AS_STR + ks + acol]));
#pragma unroll
            for (int p = 0; p < 2; p++)
                ldm_x4t(bf[p], smem_u32(&bs[(ks + brow) * CH_BS_STR + wn * 32 + p * 16 + bcol]));
#pragma unroll
            for (int im = 0; im < 4; im++) {
                mma_h(acc[im][0], af[im], &bf[0][0]);
                mma_h(acc[im][1], af[im], &bf[0][2]);
                mma_h(acc[im][2], af[im], &bf[1][0]);
                mma_h(acc[im][3], af[im], &bf[1][2]);
            }
        }
        __syncthreads();
    }

#pragma unroll
    for (int im = 0; im < 4; im++) {
        int r0 = m0 + wm * 64 + im * 16 + gid;
#pragma unroll
        for (int in = 0; in < 4; in++) {
            int c0 = n0 + wn * 32 + in * 8 + 2 * tig;
            *(float2*)(Cb + (size_t)r0 * NSEQ + c0)       = make_float2(acc[im][in][0], acc[im][in][1]);
            *(float2*)(Cb + (size_t)(r0 + 8) * NSEQ + c0) = make_float2(acc[im][in][2], acc[im][in][3]);
        }
    }
}

// ---------------- host ----------------
extern "C" void kernel_launch(void* const* d_in, const int* in_sizes, int n_in,
                              void* d_out, int out_size)
{
    const float* x     = (const float*)d_in[0];
    const float* adj   = (const float*)d_in[1];
    const float* Wf0   = (const float*)d_in[2];
    const float* Wq    = (const float*)d_in[3];
    const float* Wk    = (const float*)d_in[4];
    const float* Wv    = (const float*)d_in[5];
    const float* Wo    = (const float*)d_in[6];
    const float* gamma = (const float*)d_in[7];
    const float* beta  = (const float*)d_in[8];
    float* out_x    = (float*)d_out;
    float* out_attn = (float*)d_out + (size_t)BB * NSEQ * DD;

    float *X, *T, *RSI;
    __half *Xh, *Oh, *Qh, *Kh, *Vh, *Eh, *A0, *A1;
    __half *Wqh, *Wkh, *Wvh, *Woh;
    unsigned* MB;
    cudaGetSymbolAddress((void**)&X, g_X);
    cudaGetSymbolAddress((void**)&T, g_T);
    cudaGetSymbolAddress((void**)&Xh, g_Xh);
    cudaGetSymbolAddress((void**)&Oh, g_Oh);
    cudaGetSymbolAddress((void**)&Qh, g_Qh);
    cudaGetSymbolAddress((void**)&Kh, g_Kh);
    cudaGetSymbolAddress((void**)&Vh, g_Vh);
    cudaGetSymbolAddress((void**)&Eh, g_Eh);
    cudaGetSymbolAddress((void**)&RSI, g_RSI);
    cudaGetSymbolAddress((void**)&A0, g_A0);
    cudaGetSymbolAddress((void**)&A1, g_A1);
    cudaGetSymbolAddress((void**)&MB, g_MB);
    cudaGetSymbolAddress((void**)&Wqh, g_Wqh);
    cudaGetSymbolAddress((void**)&Wkh, g_Wkh);
    cudaGetSymbolAddress((void**)&Wvh, g_Wvh);
    cudaGetSymbolAddress((void**)&Woh, g_Woh);

    cudaFuncSetAttribute(k_pvagg, cudaFuncAttributeMaxDynamicSharedMemorySize, PVAGG_SMEM);
    cudaFuncSetAttribute(k_chain_h, cudaFuncAttributeMaxDynamicSharedMemorySize, CHAIN_SMEM);

    const int WSZ = 256 * 256;
    const int WN4 = 2 * WSZ / 4;

    k_maskbits<<<512, 256>>>(adj, MB);
    k_f2h<<<(WN4 + 255) / 256, 256>>>(Wq, Wqh, WN4);
    k_f2h<<<(WN4 + 255) / 256, 256>>>(Wk, Wkh, WN4);
    k_f2h<<<(WN4 + 255) / 256, 256>>>(Wv, Wvh, WN4);
    k_f2h<<<(WN4 + 255) / 256, 256>>>(Wo, Woh, WN4);

    // x = x @ Wf0^T (fp32, dual write X + Xh)
    k_proj<<<dim3(64, 4), 256>>>(x, Wf0, X, Xh);

    for (int i = 0; i < 2; i++) {
        // QKV projections (fp16 tensor cores)
        k_projh<<<dim3(32, 4, 3), 256>>>(Xh, Wqh + i * WSZ, Wkh + i * WSZ, Wvh + i * WSZ,
                                         Qh, Kh, Vh, (float*)nullptr);
        k_scores<<<dim3(NSEQ / 64, BB * HH), 256>>>(Qh, Kh, MB, Eh, RSI);
        k_pvagg<<<dim3(NSEQ / 32, BB), 512, PVAGG_SMEM>>>(Eh, RSI, Vh, Oh, (i == 0) ? A0 : A1);
        // T = O @ Wo^T (fp16 in, fp32 out)
        k_projh<<<dim3(32, 4, 1), 256>>>(Oh, Woh + i * WSZ, Woh + i * WSZ, Woh + i * WSZ,
                                         (half*)nullptr, (half*)nullptr, (half*)nullptr, T);
        k_addln<<<BB * NSEQ, 256>>>(X, Xh, T, gamma + i * 256, beta + i * 256);
    }

    k_chain_h<<<dim3(NSEQ / 128, NSEQ / 128, BB), 256, CHAIN_SMEM>>>(A1, A0, out_attn);

    cudaMemcpyAsync(out_x, X, (size_t)BB * NSEQ * DD * sizeof(float),
                    cudaMemcpyDeviceToDevice);
}